// round 6
// baseline (speedup 1.0000x reference)
#include <cuda_runtime.h>
#include <cstdint>

#define DIMC 2048
#define NH 16
#define HD 128
#define BATCH 4
#define SEQT 2048

// Scratch (device globals: allocation-free scratch per harness rules)
__device__ float g_k[(size_t)BATCH * NH * SEQT * HD];
__device__ float g_v[(size_t)BATCH * NH * SEQT * HD];
__device__ float g_q[(size_t)BATCH * NH * SEQT * HD];
__device__ float g_att[(size_t)BATCH * SEQT * DIMC];

__device__ __forceinline__ float tf32r(float x) {
    uint32_t u;
    asm("cvt.rna.tf32.f32 %0, %1;" : "=r"(u) : "f"(x));
    return __uint_as_float(u);
}

__device__ __forceinline__ void mma_tf32(float* c, const uint32_t* a, const uint32_t* b) {
    asm volatile(
        "mma.sync.aligned.m16n8k8.row.col.f32.tf32.tf32.f32 "
        "{%0,%1,%2,%3}, {%4,%5,%6,%7}, {%8,%9}, {%0,%1,%2,%3};"
        : "+f"(c[0]), "+f"(c[1]), "+f"(c[2]), "+f"(c[3])
        : "r"(a[0]), "r"(a[1]), "r"(a[2]), "r"(a[3]), "r"(b[0]), "r"(b[1]));
}

// ============================================================================
// Generic tf32 GEMM: C[M,N] = A[M,K] @ W[K,N] + bias
// MODE 0: plain write to Cout
// MODE 1: KV scatter (cols <2048 -> g_k head-major, >=2048 -> g_v)
// MODE 2: Q scatter (-> g_q head-major)
// BM=128, BN=128, BK=32, 256 threads (8 warps: 4 along M x 2 along N)
// ============================================================================
template <int MODE>
__global__ void __launch_bounds__(256, 2) gemm_tf32(
    const float* __restrict__ A, const float* __restrict__ W,
    const float* __restrict__ bias, float* __restrict__ Cout,
    int M, int N, int K)
{
    __shared__ float As[128][36];   // padded: (g*4 + t) banks distinct
    __shared__ float Bs[32][132];   // padded: (t*4 + g) banks distinct

    const int tid = threadIdx.x;
    const int warp = tid >> 5, lane = tid & 31;
    const int g = lane >> 2, t = lane & 3;
    const int wm = warp >> 1, wn = warp & 1;
    const int mBase = blockIdx.y * 128;
    const int nBase = blockIdx.x * 128;

    float acc[2][8][4] = {};

    for (int k0 = 0; k0 < K; k0 += 32) {
        // A tile 128x32 (1024 float4, 4 per thread)
        #pragma unroll
        for (int i = 0; i < 4; i++) {
            int f = tid + i * 256;
            int r = f >> 3, c4 = (f & 7) << 2;
            float4 v = *(const float4*)(A + (size_t)(mBase + r) * K + k0 + c4);
            As[r][c4 + 0] = tf32r(v.x); As[r][c4 + 1] = tf32r(v.y);
            As[r][c4 + 2] = tf32r(v.z); As[r][c4 + 3] = tf32r(v.w);
        }
        // B tile 32x128
        #pragma unroll
        for (int i = 0; i < 4; i++) {
            int f = tid + i * 256;
            int r = f >> 5, c4 = (f & 31) << 2;
            float4 v = *(const float4*)(W + (size_t)(k0 + r) * N + nBase + c4);
            Bs[r][c4 + 0] = tf32r(v.x); Bs[r][c4 + 1] = tf32r(v.y);
            Bs[r][c4 + 2] = tf32r(v.z); Bs[r][c4 + 3] = tf32r(v.w);
        }
        __syncthreads();

        #pragma unroll
        for (int ks = 0; ks < 4; ks++) {
            const int kk = ks * 8;
            uint32_t a[2][4], b[8][2];
            #pragma unroll
            for (int mt = 0; mt < 2; mt++) {
                const int rb = wm * 32 + mt * 16;
                a[mt][0] = __float_as_uint(As[rb + g][kk + t]);
                a[mt][1] = __float_as_uint(As[rb + g + 8][kk + t]);
                a[mt][2] = __float_as_uint(As[rb + g][kk + t + 4]);
                a[mt][3] = __float_as_uint(As[rb + g + 8][kk + t + 4]);
            }
            #pragma unroll
            for (int nt = 0; nt < 8; nt++) {
                const int cb = wn * 64 + nt * 8;
                b[nt][0] = __float_as_uint(Bs[kk + t][cb + g]);
                b[nt][1] = __float_as_uint(Bs[kk + t + 4][cb + g]);
            }
            #pragma unroll
            for (int mt = 0; mt < 2; mt++)
                #pragma unroll
                for (int nt = 0; nt < 8; nt++)
                    mma_tf32(acc[mt][nt], a[mt], b[nt]);
        }
        __syncthreads();
    }

    // Epilogue
    #pragma unroll
    for (int mt = 0; mt < 2; mt++) {
        #pragma unroll
        for (int nt = 0; nt < 8; nt++) {
            #pragma unroll
            for (int e = 0; e < 4; e++) {
                const int r = mBase + wm * 32 + mt * 16 + g + (e >> 1) * 8;
                const int c = nBase + wn * 64 + nt * 8 + t * 2 + (e & 1);
                float val = acc[mt][nt][e] + bias[c];
                if (MODE == 0) {
                    Cout[(size_t)r * N + c] = val;
                } else if (MODE == 1) {
                    const int b_ = r >> 11, tt = r & 2047;
                    const int cc = c & 2047;
                    const int h = cc >> 7, d = cc & 127;
                    float* dst = (c < 2048) ? g_k : g_v;
                    dst[(((size_t)(b_ * NH + h)) * SEQT + tt) * HD + d] = val;
                } else {
                    const int b_ = r >> 11, tt = r & 2047;
                    const int h = c >> 7, d = c & 127;
                    g_q[(((size_t)(b_ * NH + h)) * SEQT + tt) * HD + d] = val;
                }
            }
        }
    }
}

// ============================================================================
// Flash attention (causal), tf32 mma.
// Block: 256 threads (8 warps), 128 q-rows per block, 64-key tiles.
// Each warp owns 16 q-rows. grid = (T/128, B*NH).
// ============================================================================
__global__ void __launch_bounds__(256, 1) attn_kernel()
{
    extern __shared__ float sm[];
    float* Qs = sm;                    // [128][132]
    float* Ks = Qs + 128 * 132;        // [64][132]
    float* Vs = Ks + 64 * 132;         // [64][132]
    float* Ps = Vs + 64 * 132;         // [128][68]

    const int bh = blockIdx.y;         // 0..63
    const int qt = blockIdx.x;         // 0..15
    const int qBase = qt * 128;
    const int tid = threadIdx.x, warp = tid >> 5, lane = tid & 31;
    const int g = lane >> 2, t = lane & 3;
    const int rowW = warp * 16;
    const float scale = 0.08838834764831845f;  // 1/sqrt(128)

    const float* Qg = g_q + (size_t)bh * SEQT * HD;
    const float* Kg = g_k + (size_t)bh * SEQT * HD;
    const float* Vg = g_v + (size_t)bh * SEQT * HD;

    // Load Q tile (pre-scaled, tf32-rounded)
    #pragma unroll
    for (int i = 0; i < 16; i++) {
        int f = tid + i * 256;
        int r = f >> 5, c4 = (f & 31) << 2;
        float4 v = *(const float4*)(Qg + (size_t)(qBase + r) * HD + c4);
        Qs[r * 132 + c4 + 0] = tf32r(v.x * scale);
        Qs[r * 132 + c4 + 1] = tf32r(v.y * scale);
        Qs[r * 132 + c4 + 2] = tf32r(v.z * scale);
        Qs[r * 132 + c4 + 3] = tf32r(v.w * scale);
    }

    float o[16][4] = {};
    float m_[2], l_[2];
    m_[0] = m_[1] = -1e30f;
    l_[0] = l_[1] = 0.0f;

    const int nkt = 2 * qt + 2;
    for (int kt = 0; kt < nkt; kt++) {
        const int kBase = kt * 64;
        // Load K,V tiles (64x128 each)
        #pragma unroll
        for (int i = 0; i < 8; i++) {
            int f = tid + i * 256;
            int r = f >> 5, c4 = (f & 31) << 2;
            float4 kv = *(const float4*)(Kg + (size_t)(kBase + r) * HD + c4);
            Ks[r * 132 + c4 + 0] = tf32r(kv.x); Ks[r * 132 + c4 + 1] = tf32r(kv.y);
            Ks[r * 132 + c4 + 2] = tf32r(kv.z); Ks[r * 132 + c4 + 3] = tf32r(kv.w);
            float4 vv = *(const float4*)(Vg + (size_t)(kBase + r) * HD + c4);
            Vs[r * 132 + c4 + 0] = tf32r(vv.x); Vs[r * 132 + c4 + 1] = tf32r(vv.y);
            Vs[r * 132 + c4 + 2] = tf32r(vv.z); Vs[r * 132 + c4 + 3] = tf32r(vv.w);
        }
        __syncthreads();

        // S = Q @ K^T  (warp: 16 rows x 64 keys)
        float s[8][4] = {};
        #pragma unroll
        for (int ks = 0; ks < 16; ks++) {
            const int kk = ks * 8;
            uint32_t a[4];
            a[0] = __float_as_uint(Qs[(rowW + g) * 132 + kk + t]);
            a[1] = __float_as_uint(Qs[(rowW + g + 8) * 132 + kk + t]);
            a[2] = __float_as_uint(Qs[(rowW + g) * 132 + kk + t + 4]);
            a[3] = __float_as_uint(Qs[(rowW + g + 8) * 132 + kk + t + 4]);
            #pragma unroll
            for (int nt = 0; nt < 8; nt++) {
                uint32_t b[2];
                b[0] = __float_as_uint(Ks[(nt * 8 + g) * 132 + kk + t]);
                b[1] = __float_as_uint(Ks[(nt * 8 + g) * 132 + kk + t + 4]);
                mma_tf32(s[nt], a, b);
            }
        }

        // Causal mask for diagonal tiles
        if (kt >= 2 * qt) {
            #pragma unroll
            for (int nt = 0; nt < 8; nt++)
                #pragma unroll
                for (int e = 0; e < 4; e++) {
                    const int key = kBase + nt * 8 + t * 2 + (e & 1);
                    const int qr = qBase + rowW + g + (e >> 1) * 8;
                    if (key > qr) s[nt][e] = -1e30f;
                }
        }

        // Online softmax (per thread: rows g and g+8)
        float mnew[2];
        #pragma unroll
        for (int rr = 0; rr < 2; rr++) {
            float mx = -1e30f;
            #pragma unroll
            for (int nt = 0; nt < 8; nt++)
                mx = fmaxf(mx, fmaxf(s[nt][rr * 2], s[nt][rr * 2 + 1]));
            mx = fmaxf(mx, __shfl_xor_sync(0xffffffffu, mx, 1));
            mx = fmaxf(mx, __shfl_xor_sync(0xffffffffu, mx, 2));
            mnew[rr] = fmaxf(m_[rr], mx);
        }
        float corr[2];
        corr[0] = __expf(m_[0] - mnew[0]);
        corr[1] = __expf(m_[1] - mnew[1]);

        float rs[2] = {0.0f, 0.0f};
        #pragma unroll
        for (int nt = 0; nt < 8; nt++)
            #pragma unroll
            for (int e = 0; e < 4; e++) {
                const int rr = e >> 1;
                float p = __expf(s[nt][e] - mnew[rr]);
                s[nt][e] = p;
                rs[rr] += p;
            }
        #pragma unroll
        for (int rr = 0; rr < 2; rr++) {
            float v = rs[rr];
            v += __shfl_xor_sync(0xffffffffu, v, 1);
            v += __shfl_xor_sync(0xffffffffu, v, 2);
            l_[rr] = l_[rr] * corr[rr] + v;
            m_[rr] = mnew[rr];
        }

        // Rescale O accumulators
        #pragma unroll
        for (int nt = 0; nt < 16; nt++)
            #pragma unroll
            for (int e = 0; e < 4; e++)
                o[nt][e] *= corr[e >> 1];

        // P -> smem (C-fragment layout != A-fragment layout, round-trip)
        #pragma unroll
        for (int nt = 0; nt < 8; nt++) {
            const int c = nt * 8 + t * 2;
            Ps[(rowW + g) * 68 + c]     = tf32r(s[nt][0]);
            Ps[(rowW + g) * 68 + c + 1] = tf32r(s[nt][1]);
            Ps[(rowW + g + 8) * 68 + c]     = tf32r(s[nt][2]);
            Ps[(rowW + g + 8) * 68 + c + 1] = tf32r(s[nt][3]);
        }
        __syncwarp();

        // O += P @ V  (k = 64 keys, n = 128 dims)
        #pragma unroll
        for (int ks = 0; ks < 8; ks++) {
            const int kk = ks * 8;
            uint32_t a[4];
            a[0] = __float_as_uint(Ps[(rowW + g) * 68 + kk + t]);
            a[1] = __float_as_uint(Ps[(rowW + g + 8) * 68 + kk + t]);
            a[2] = __float_as_uint(Ps[(rowW + g) * 68 + kk + t + 4]);
            a[3] = __float_as_uint(Ps[(rowW + g + 8) * 68 + kk + t + 4]);
            #pragma unroll
            for (int nt = 0; nt < 16; nt++) {
                uint32_t b[2];
                b[0] = __float_as_uint(Vs[(kk + t) * 132 + nt * 8 + g]);
                b[1] = __float_as_uint(Vs[(kk + t + 4) * 132 + nt * 8 + g]);
                mma_tf32(o[nt], a, b);
            }
        }
        __syncthreads();
    }

    // Write normalized output to g_att[b, row, h*128 + d]
    const int b_ = bh >> 4, h = bh & 15;
    const float inv0 = 1.0f / l_[0], inv1 = 1.0f / l_[1];
    #pragma unroll
    for (int nt = 0; nt < 16; nt++)
        #pragma unroll
        for (int e = 0; e < 4; e++) {
            const int rr = e >> 1;
            const int row = qBase + rowW + g + rr * 8;
            const int d = nt * 8 + t * 2 + (e & 1);
            g_att[((size_t)b_ * SEQT + row) * DIMC + h * HD + d] =
                o[nt][e] * (rr ? inv1 : inv0);
        }
}

extern "C" void kernel_launch(void* const* d_in, const int* in_sizes, int n_in,
                              void* d_out, int out_size)
{
    const float* enc = (const float*)d_in[0];
    const float* dec = (const float*)d_in[1];
    const float* Wkv = (const float*)d_in[2];
    const float* bkv = (const float*)d_in[3];
    const float* Wq  = (const float*)d_in[4];
    const float* bq  = (const float*)d_in[5];
    const float* Wo  = (const float*)d_in[6];
    const float* bo  = (const float*)d_in[7];
    float* out = (float*)d_out;

    void* attPtr = nullptr;
    cudaGetSymbolAddress(&attPtr, g_att);

    const int M = BATCH * SEQT;  // 8192
    dim3 blk(256);

    // 1) KV projection -> g_k, g_v (head-major)
    gemm_tf32<1><<<dim3((2 * DIMC) / 128, M / 128), blk>>>(
        enc, Wkv, bkv, nullptr, M, 2 * DIMC, DIMC);
    // 2) Q projection -> g_q (head-major)
    gemm_tf32<2><<<dim3(DIMC / 128, M / 128), blk>>>(
        dec, Wq, bq, nullptr, M, DIMC, DIMC);

    // 3) Causal flash attention -> g_att
    const size_t ATT_SMEM = (size_t)(128 * 132 + 64 * 132 + 64 * 132 + 128 * 68) * sizeof(float);
    cudaFuncSetAttribute((const void*)attn_kernel,
                         cudaFuncAttributeMaxDynamicSharedMemorySize, (int)ATT_SMEM);
    attn_kernel<<<dim3(SEQT / 128, BATCH * NH), blk, ATT_SMEM>>>();

    // 4) Output projection -> d_out
    gemm_tf32<0><<<dim3(DIMC / 128, M / 128), blk>>>(
        (const float*)attPtr, Wo, bo, out, M, DIMC, DIMC);
}